// round 4
// baseline (speedup 1.0000x reference)
#include <cuda_runtime.h>
#include <math.h>

#define HW     128
#define NPIX   (HW*HW)        // 16384
#define BSZ    128
#define NPACK  128            // packed complex images
#define PITCHF 129            // smem row pitch in floats (odd => conflict-free r-strided access)
#define GK     64             // GEMM K-splits (chunk = 256)

// ---------------- device scratch ----------------
__device__ float  g_norm[2*BSZ];
__device__ float  g_dot_part[GK*BSZ*BSZ];         // 4 MB partial dots
__device__ float  g_dist[BSZ*BSZ];
__device__ float  g_lse[BSZ];
__device__ float  g_psd[NPACK*NPIX];              // per packed-image |Z|^2 (8 MB)
__device__ float  g_S[NPIX];                      // sum over images of |Z|^2

// ---------------- FFT helpers ----------------
__device__ __forceinline__ void cmul_ip(float& vr, float& vi, float2 w){
    float t = vr;
    vr = vr*w.x - vi*w.y;
    vi = t*w.y + vi*w.x;
}
// 4-pt DFT, natural-order outputs (X0..X3) written back to x0..x3
__device__ __forceinline__ void bf4(float&x0r,float&x0i,float&x1r,float&x1i,
                                    float&x2r,float&x2i,float&x3r,float&x3i){
    float t0r=x0r+x2r, t0i=x0i+x2i, t1r=x0r-x2r, t1i=x0i-x2i;
    float t2r=x1r+x3r, t2i=x1i+x3i, t3r=x1r-x3r, t3i=x1i-x3i;
    x0r=t0r+t2r; x0i=t0i+t2i;
    x1r=t1r+t3i; x1i=t1i-t3r;     // t1 + (-i)*t3
    x2r=t0r-t2r; x2i=t0i-t2i;
    x3r=t1r-t3i; x3i=t1i+t3r;     // t1 + (+i)*t3
}

// 16-pt DFT (DIF radix-4 x radix-4) fully in registers.
// Input x[s] natural order; output: slot (4*e1 + e2) holds frequency d = e1 + 4*e2.
__device__ __forceinline__ void fft16(float* xr, float* xi, const float2* tw){
#pragma unroll
    for (int s0 = 0; s0 < 4; s0++){
        bf4(xr[s0],xi[s0], xr[s0+4],xi[s0+4], xr[s0+8],xi[s0+8], xr[s0+12],xi[s0+12]);
        if (s0){
            cmul_ip(xr[s0+4],  xi[s0+4],  tw[8*s0]);    // w16^{s0}
            cmul_ip(xr[s0+8],  xi[s0+8],  tw[16*s0]);   // w16^{2 s0}
            cmul_ip(xr[s0+12], xi[s0+12], tw[24*s0]);   // w16^{3 s0}
        }
    }
#pragma unroll
    for (int e1 = 0; e1 < 4; e1++)
        bf4(xr[4*e1],xi[4*e1], xr[4*e1+1],xi[4*e1+1],
            xr[4*e1+2],xi[4*e1+2], xr[4*e1+3],xi[4*e1+3]);
}

// 8-pt DFT (DIF radix-2 x radix-4) in registers.
// Input y[n] natural; output slot (4*f1 + f2) holds k' = f1 + 2*f2.
__device__ __forceinline__ void fft8(float* yr, float* yi, const float2* tw){
#pragma unroll
    for (int n2 = 0; n2 < 4; n2++){
        float ur=yr[n2], ui=yi[n2], vr=yr[n2+4], vi=yi[n2+4];
        yr[n2]=ur+vr; yi[n2]=ui+vi;
        float dr=ur-vr, di=ui-vi;
        if (n2 == 0){ yr[n2+4]=dr; yi[n2+4]=di; }
        else {
            float2 w = tw[16*n2];                       // w8^{n2}
            yr[n2+4]=dr*w.x-di*w.y; yi[n2+4]=dr*w.y+di*w.x;
        }
    }
    bf4(yr[0],yi[0], yr[1],yi[1], yr[2],yi[2], yr[3],yi[3]);
    bf4(yr[4],yi[4], yr[5],yi[5], yr[6],yi[6], yr[7],yi[7]);
}

// stored index p = 8*d1 + k'  ->  frequency k = d1 + 16*k'
__device__ __forceinline__ int sig2(int p){ return (p>>3) | ((p&7)<<4); }
__device__ __forceinline__ int isig2(int k){ return ((k&15)<<3) | (k>>4); }
__device__ __forceinline__ int tau2(int p){ return isig2((128 - sig2(p)) & 127); }

// ---------------- GEMM: dot(a_i, b_j), 128x128xK, K-split 64 ----------------
// grid (2, 1, GK): blockIdx.x = 64-wide N tile, blockIdx.z = K chunk of 256.
__global__ __launch_bounds__(256) void dot_kernel(const float* __restrict__ A, const float* __restrict__ B) {
    __shared__ float As[16][132];
    __shared__ float Bs[16][68];
    int tid = threadIdx.x;
    int tx = tid & 15, ty = tid >> 4;
    int nb = blockIdx.x * 64;
    int k0 = blockIdx.z * 256;

    float acc[8][4];
#pragma unroll
    for (int r = 0; r < 8; r++)
#pragma unroll
        for (int c = 0; c < 4; c++) acc[r][c] = 0.f;

    for (int ks = 0; ks < 16; ks++) {
        int kb = k0 + ks * 16;
        __syncthreads();
#pragma unroll
        for (int i = 0; i < 2; i++) {
            int idx = tid + i * 256;
            int row = idx >> 2, kq = idx & 3;
            float4 v = *reinterpret_cast<const float4*>(A + (size_t)row * NPIX + kb + kq * 4);
            As[kq*4+0][row] = v.x; As[kq*4+1][row] = v.y;
            As[kq*4+2][row] = v.z; As[kq*4+3][row] = v.w;
        }
        {
            int row = tid >> 2, kq = tid & 3;
            float4 v = *reinterpret_cast<const float4*>(B + (size_t)(nb + row) * NPIX + kb + kq * 4);
            Bs[kq*4+0][row] = v.x; Bs[kq*4+1][row] = v.y;
            Bs[kq*4+2][row] = v.z; Bs[kq*4+3][row] = v.w;
        }
        __syncthreads();
#pragma unroll
        for (int kk = 0; kk < 16; kk++) {
            float4 a0 = *reinterpret_cast<const float4*>(&As[kk][ty*8]);
            float4 a1 = *reinterpret_cast<const float4*>(&As[kk][ty*8+4]);
            float4 b0 = *reinterpret_cast<const float4*>(&Bs[kk][tx*4]);
            float ra[8] = {a0.x,a0.y,a0.z,a0.w,a1.x,a1.y,a1.z,a1.w};
            float rb[4] = {b0.x,b0.y,b0.z,b0.w};
#pragma unroll
            for (int r = 0; r < 8; r++)
#pragma unroll
                for (int c = 0; c < 4; c++) acc[r][c] += ra[r] * rb[c];
        }
    }
    float* outp = g_dot_part + (size_t)blockIdx.z * BSZ * BSZ;
#pragma unroll
    for (int r = 0; r < 8; r++) {
        float4 v = make_float4(acc[r][0], acc[r][1], acc[r][2], acc[r][3]);
        *reinterpret_cast<float4*>(outp + (ty*8 + r) * BSZ + nb + tx*4) = v;
    }
}

// ---------------- Dist + per-row logsumexp ----------------
__global__ void dist_lse_kernel() {
    int i = blockIdx.x, j = threadIdx.x;
    float dot = 0.f;
#pragma unroll 8
    for (int s = 0; s < GK; s++) dot += g_dot_part[(size_t)s*BSZ*BSZ + i*BSZ + j];
    float d2 = g_norm[i] + g_norm[BSZ + j] - 2.f * dot;
    float d = sqrtf(fmaxf(d2, 0.f));
    g_dist[i*BSZ + j] = d;

    __shared__ float red[BSZ];
    red[j] = d; __syncthreads();
    for (int off = 64; off > 0; off >>= 1) {
        if (j < off) red[j] = fmaxf(red[j], red[j + off]);
        __syncthreads();
    }
    float mx = red[0]; __syncthreads();
    red[j] = expf(d - mx); __syncthreads();
    for (int off = 64; off > 0; off >>= 1) {
        if (j < off) red[j] += red[j + off];
        __syncthreads();
    }
    if (j == 0) g_lse[i] = mx + logf(red[0]);
}

// ---------------- packed 2D FFT, register radix-16x8, + norms + |Z|^2 ----------------
__global__ __launch_bounds__(1024, 1) void fft_psd_kernel(const float* __restrict__ x1, const float* __restrict__ x2) {
    extern __shared__ float sm[];
    float* SRe = sm;
    float* SIm = sm + 128*PITCHF;
    __shared__ float2 tw[128];
    __shared__ float nb1[32], nb2[32];

    int b = blockIdx.x;
    int tid = threadIdx.x;
    const float* sa = x1 + (size_t)b*NPIX;
    const float* sb = x2 + (size_t)b*NPIX;

    if (tid < 128) {
        float sn, cs;
        sincospif((float)tid / 64.f, &sn, &cs);
        tw[tid] = make_float2(cs, -sn);                 // W128^tid
    }

    // ===== phase 1: rows, 16-pt stage (gmem -> regs -> smem, skewed) =====
    int r = tid >> 3, n = tid & 7;                      // 128 rows x 8 lanes
    float xr[16], xi[16];
    float s1 = 0.f, s2 = 0.f;
#pragma unroll
    for (int s = 0; s < 16; s++) {
        float a  = sa[r*128 + n + 8*s];
        float bb = sb[r*128 + n + 8*s];
        xr[s] = a; xi[s] = bb;
        s1 += a*a; s2 += bb*bb;
    }
    // stage norm partial sums
#pragma unroll
    for (int o = 16; o; o >>= 1) {
        s1 += __shfl_down_sync(0xffffffffu, s1, o);
        s2 += __shfl_down_sync(0xffffffffu, s2, o);
    }
    if ((tid & 31) == 0) { nb1[tid>>5] = s1; nb2[tid>>5] = s2; }
    __syncthreads();                                    // tw ready, norms staged
    if (tid < 32) {
        float a = nb1[tid], c = nb2[tid];
#pragma unroll
        for (int o = 16; o; o >>= 1) {
            a += __shfl_down_sync(0xffffffffu, a, o);
            c += __shfl_down_sync(0xffffffffu, c, o);
        }
        if (tid == 0) { g_norm[b] = a; g_norm[b + BSZ] = c; }
    }

    fft16(xr, xi, tw);
    // apply W128^{n*d}, write with d-block skew (d + r) & 15
#pragma unroll
    for (int sl = 0; sl < 16; sl++) {
        int e1 = sl >> 2, e2 = sl & 3;
        int d = e1 + 4*e2;
        float vr = xr[sl], vi = xi[sl];
        if (d) cmul_ip(vr, vi, tw[n*d]);
        int col = 8*((d + r) & 15) + n;
        SRe[r*PITCHF + col] = vr;
        SIm[r*PITCHF + col] = vi;
    }
    __syncthreads();

    // ===== phase 2: rows, 8-pt stage (smem -> regs -> smem, unskew) =====
    {
        int r2 = tid & 127, d1a = tid >> 7;             // d1a in [0,8)
        float yr[16], yi[16];
#pragma unroll
        for (int h = 0; h < 2; h++) {
            int d1 = d1a + 8*h;
            int cb = r2*PITCHF + 8*((d1 + r2) & 15);
#pragma unroll
            for (int k = 0; k < 8; k++) { yr[8*h+k] = SRe[cb+k]; yi[8*h+k] = SIm[cb+k]; }
        }
        __syncthreads();                                // all reads before in-place writes
#pragma unroll
        for (int h = 0; h < 2; h++) {
            fft8(yr + 8*h, yi + 8*h, tw);
            int ob = r2*PITCHF + 8*(d1a + 8*h);
#pragma unroll
            for (int f2 = 0; f2 < 4; f2++) {
                SRe[ob + 2*f2]     = yr[8*h + f2];      // k' = 2*f2
                SIm[ob + 2*f2]     = yi[8*h + f2];
                SRe[ob + 2*f2 + 1] = yr[8*h + 4 + f2];  // k' = 1 + 2*f2
                SIm[ob + 2*f2 + 1] = yi[8*h + 4 + f2];
            }
        }
    }
    __syncthreads();

    // ===== phase 3: cols, 16-pt stage (in-place per-thread, plain layout) =====
    {
        int c = tid & 127, n3 = tid >> 7;               // 128 cols x 8 lanes
        float zr[16], zi[16];
#pragma unroll
        for (int s = 0; s < 16; s++) {
            int m = n3 + 8*s;
            zr[s] = SRe[m*PITCHF + c];
            zi[s] = SIm[m*PITCHF + c];
        }
        fft16(zr, zi, tw);
#pragma unroll
        for (int sl = 0; sl < 16; sl++) {
            int e1 = sl >> 2, e2 = sl & 3;
            int d = e1 + 4*e2;
            float vr = zr[sl], vi = zi[sl];
            if (d) cmul_ip(vr, vi, tw[n3*d]);
            SRe[(8*d + n3)*PITCHF + c] = vr;
            SIm[(8*d + n3)*PITCHF + c] = vi;
        }
    }
    __syncthreads();

    // ===== phase 4: cols, 8-pt stage + |Z|^2 -> gmem =====
    {
        int c4 = tid & 127, d1c = tid >> 7;             // d1c in [0,8)
#pragma unroll
        for (int h = 0; h < 2; h++) {
            int d1 = d1c + 8*h;
            float wr[8], wi[8];
#pragma unroll
            for (int k = 0; k < 8; k++) {
                wr[k] = SRe[(8*d1 + k)*PITCHF + c4];
                wi[k] = SIm[(8*d1 + k)*PITCHF + c4];
            }
            fft8(wr, wi, tw);
            float* dst = g_psd + (size_t)b*NPIX + c4;
#pragma unroll
            for (int f2 = 0; f2 < 4; f2++) {
                dst[(8*d1 + 2*f2    )*128] = wr[f2]*wr[f2] + wi[f2]*wi[f2];
                dst[(8*d1 + 2*f2 + 1)*128] = wr[4+f2]*wr[4+f2] + wi[4+f2]*wi[4+f2];
            }
        }
    }
}

// ---------------- S(p) = sum over packed images of |Z|^2 ----------------
__global__ void psd_reduce_kernel() {
    int p = blockIdx.x * 128 + threadIdx.x;
    float s0=0.f, s1=0.f, s2=0.f, s3=0.f;
    for (int img = 0; img < NPACK; img += 4) {
        s0 += g_psd[(size_t)(img  )*NPIX + p];
        s1 += g_psd[(size_t)(img+1)*NPIX + p];
        s2 += g_psd[(size_t)(img+2)*NPIX + p];
        s3 += g_psd[(size_t)(img+3)*NPIX + p];
    }
    g_S[p] = (s0 + s1) + (s2 + s3);
}

// ---------------- fused stats (+ce) + final scalar, one CTA ----------------
__global__ __launch_bounds__(1024) void stats_final_kernel(float* __restrict__ out) {
    int t = threadIdx.x;
    __shared__ double red[32];

    double sl = 0.0, sa2 = 0.0;
#pragma unroll 4
    for (int i = 0; i < 16; i++) {
        int p = t + 1024*i;
        int pr = p >> 7, pc = p & 127;
        int q = tau2(pr)*128 + tau2(pc);
        double avg = ((double)g_S[p] + (double)g_S[q]) * (1.0/512.0);
        sl += log(avg);
        sa2 += avg;
    }
    double ce = (t < 128) ? (double)(g_lse[t] - g_dist[t*BSZ + t]) : 0.0;

    double vals[3] = {sl, sa2, ce};
    double tot[3];
#pragma unroll
    for (int v = 0; v < 3; v++) {
        double x = vals[v];
#pragma unroll
        for (int o = 16; o; o >>= 1) x += __shfl_down_sync(0xffffffffu, x, o);
        if ((t & 31) == 0) red[t >> 5] = x;
        __syncthreads();
        if (t < 32) {
            double y = red[t];
#pragma unroll
            for (int o = 16; o; o >>= 1) y += __shfl_down_sync(0xffffffffu, y, o);
            if (t == 0) red[0] = y;
        }
        __syncthreads();
        tot[v] = red[0];
        __syncthreads();
    }

    if (t == 0) {
        double r = tot[0] / 16384.0 - log(tot[1] / 16384.0);
        out[0] = (float)(tot[2] / 128.0 - 0.1 * r);
    }
}

// ---------------- launch ----------------
extern "C" void kernel_launch(void* const* d_in, const int* in_sizes, int n_in,
                              void* d_out, int out_size) {
    const float* x1 = (const float*)d_in[0];
    const float* x2 = (const float*)d_in[1];
    float* out = (float*)d_out;

    const int smem = 2 * 128 * PITCHF * (int)sizeof(float);   // 132096 B
    cudaFuncSetAttribute(fft_psd_kernel, cudaFuncAttributeMaxDynamicSharedMemorySize, smem);

    dot_kernel<<<dim3(2, 1, GK), 256>>>(x1, x2);
    fft_psd_kernel<<<NPACK, 1024, smem>>>(x1, x2);
    dist_lse_kernel<<<BSZ, BSZ>>>();
    psd_reduce_kernel<<<128, 128>>>();
    stats_final_kernel<<<1, 1024>>>(out);
}

// round 6
// speedup vs baseline: 3.8509x; 3.8509x over previous
#include <cuda_runtime.h>
#include <math.h>

#define HW     128
#define NPIX   (HW*HW)        // 16384
#define BSZ    128
#define NPACK  128            // packed complex images
#define PITCH  129            // smem row pitch in float2 (conflict padding)
#define GK     64             // GEMM K-splits (chunk = 256)

// ---------------- device scratch ----------------
__device__ float  g_norm[2*BSZ];
__device__ float  g_dot_part[GK*BSZ*BSZ];         // 4 MB partial dots
__device__ float  g_dist[BSZ*BSZ];
__device__ float  g_lse[BSZ];
__device__ float  g_psd[NPACK*NPIX];              // per packed-image |Z|^2 (8 MB)
__device__ float  g_S[8*NPIX];                    // image-group partial sums
__device__ double g_red_log[128];
__device__ double g_red_avg[128];

// ---------------- f32x2 packed helpers ----------------
__device__ __forceinline__ unsigned long long pk2(float x){
    unsigned long long r; asm("mov.b64 %0, {%1, %1};" : "=l"(r) : "f"(x)); return r;
}
__device__ __forceinline__ void upk2(unsigned long long v, float& lo, float& hi){
    asm("mov.b64 {%0, %1}, %2;" : "=f"(lo), "=f"(hi) : "l"(v));
}
__device__ __forceinline__ void ffma2(unsigned long long& c, unsigned long long a, unsigned long long b){
    asm("fma.rn.f32x2 %0, %1, %2, %3;" : "=l"(c) : "l"(a), "l"(b), "l"(c));
}

// ---------------- complex helpers ----------------
__device__ __forceinline__ float2 cadd(float2 a, float2 b){ return make_float2(a.x+b.x, a.y+b.y); }
__device__ __forceinline__ float2 csub(float2 a, float2 b){ return make_float2(a.x-b.x, a.y-b.y); }
__device__ __forceinline__ float2 cmul(float2 a, float2 b){ return make_float2(a.x*b.x - a.y*b.y, a.x*b.y + a.y*b.x); }

__device__ __forceinline__ void r4(float2&u0,float2&u1,float2&u2,float2&u3,
                                   float2 w1, float2 w2, float2 w3){
    float2 t0 = cadd(u0,u2), t1 = csub(u0,u2);
    float2 t2 = cadd(u1,u3), t3 = csub(u1,u3);
    float2 t3m = make_float2(t3.y, -t3.x);        // -i * t3
    u0 = cadd(t0,t2);
    u1 = cmul(cadd(t1,t3m), w1);
    u2 = cmul(csub(t0,t2), w2);
    u3 = cmul(csub(t1,t3m), w3);
}
__device__ __forceinline__ void r4nw(float2&u0,float2&u1,float2&u2,float2&u3){
    float2 t0 = cadd(u0,u2), t1 = csub(u0,u2);
    float2 t2 = cadd(u1,u3), t3 = csub(u1,u3);
    float2 t3m = make_float2(t3.y, -t3.x);
    u0 = cadd(t0,t2);
    u1 = cadd(t1,t3m);
    u2 = csub(t0,t2);
    u3 = csub(t1,t3m);
}
__device__ __forceinline__ void r2(float2&u0,float2&u1){
    float2 a = cadd(u0,u1), b = csub(u0,u1);
    u0 = a; u1 = b;
}

// DIF digit-reversal permutation for stage order (radix 4,4,4,2):
__device__ __forceinline__ int sigp(int p){
    return (p>>5) + (((p>>3)&3)<<2) + (((p>>1)&3)<<4) + ((p&1)<<6);
}
__device__ __forceinline__ int isigp(int k){
    return ((k&3)<<5) + (((k>>2)&3)<<3) + (((k>>4)&3)<<1) + (k>>6);
}
__device__ __forceinline__ int tau(int p){
    return isigp((128 - sigp(p)) & 127);
}

// ---------------- GEMM: dot(a_i, b_j), f32x2 packed, K-split 64 ----------------
// grid (2, 1, GK): blockIdx.x = 64-wide N tile, blockIdx.z = K chunk of 256.
// block 256 threads, 8x4 micro-tile (rows packed in pairs) -> 128x64 per block.
__global__ __launch_bounds__(256) void dot_kernel(const float* __restrict__ A, const float* __restrict__ B) {
    __shared__ __align__(16) float As[16][132];
    __shared__ __align__(16) float Bs[16][68];
    int tid = threadIdx.x;
    int tx = tid & 15, ty = tid >> 4;
    int nb = blockIdx.x * 64;
    int k0 = blockIdx.z * 256;

    unsigned long long acc[4][4];
#pragma unroll
    for (int rp = 0; rp < 4; rp++)
#pragma unroll
        for (int c = 0; c < 4; c++) acc[rp][c] = 0ull;

    for (int ks = 0; ks < 16; ks++) {
        int kb = k0 + ks * 16;
        __syncthreads();
#pragma unroll
        for (int i = 0; i < 2; i++) {
            int idx = tid + i * 256;
            int row = idx >> 2, kq = idx & 3;
            float4 v = *reinterpret_cast<const float4*>(A + (size_t)row * NPIX + kb + kq * 4);
            As[kq*4+0][row] = v.x; As[kq*4+1][row] = v.y;
            As[kq*4+2][row] = v.z; As[kq*4+3][row] = v.w;
        }
        {
            int row = tid >> 2, kq = tid & 3;
            float4 v = *reinterpret_cast<const float4*>(B + (size_t)(nb + row) * NPIX + kb + kq * 4);
            Bs[kq*4+0][row] = v.x; Bs[kq*4+1][row] = v.y;
            Bs[kq*4+2][row] = v.z; Bs[kq*4+3][row] = v.w;
        }
        __syncthreads();
#pragma unroll
        for (int kk = 0; kk < 16; kk++) {
            // A row-pairs, already packed {row2rp, row2rp+1} in memory
            const double2* ap = reinterpret_cast<const double2*>(&As[kk][ty*8]);
            double2 a01 = ap[0], a23 = ap[1];
            unsigned long long a2[4];
            a2[0] = __double_as_longlong(a01.x);
            a2[1] = __double_as_longlong(a01.y);
            a2[2] = __double_as_longlong(a23.x);
            a2[3] = __double_as_longlong(a23.y);
            float4 b0 = *reinterpret_cast<const float4*>(&Bs[kk][tx*4]);
            unsigned long long b2[4];
            b2[0] = pk2(b0.x); b2[1] = pk2(b0.y); b2[2] = pk2(b0.z); b2[3] = pk2(b0.w);
#pragma unroll
            for (int rp = 0; rp < 4; rp++)
#pragma unroll
                for (int c = 0; c < 4; c++) ffma2(acc[rp][c], a2[rp], b2[c]);
        }
    }
    float* outp = g_dot_part + (size_t)blockIdx.z * BSZ * BSZ;
#pragma unroll
    for (int rp = 0; rp < 4; rp++) {
        float lo0, hi0, lo1, hi1, lo2, hi2, lo3, hi3;
        upk2(acc[rp][0], lo0, hi0); upk2(acc[rp][1], lo1, hi1);
        upk2(acc[rp][2], lo2, hi2); upk2(acc[rp][3], lo3, hi3);
        *reinterpret_cast<float4*>(outp + (ty*8 + 2*rp    ) * BSZ + nb + tx*4) = make_float4(lo0, lo1, lo2, lo3);
        *reinterpret_cast<float4*>(outp + (ty*8 + 2*rp + 1) * BSZ + nb + tx*4) = make_float4(hi0, hi1, hi2, hi3);
    }
}

// ---------------- Dist + per-row logsumexp ----------------
__global__ void dist_lse_kernel() {
    int i = blockIdx.x, j = threadIdx.x;
    float dot = 0.f;
#pragma unroll 16
    for (int s = 0; s < GK; s++) dot += g_dot_part[(size_t)s*BSZ*BSZ + i*BSZ + j];
    float d2 = g_norm[i] + g_norm[BSZ + j] - 2.f * dot;
    float d = sqrtf(fmaxf(d2, 0.f));
    g_dist[i*BSZ + j] = d;

    __shared__ float red[BSZ];
    red[j] = d; __syncthreads();
    for (int off = 64; off > 0; off >>= 1) {
        if (j < off) red[j] = fmaxf(red[j], red[j + off]);
        __syncthreads();
    }
    float mx = red[0]; __syncthreads();
    red[j] = expf(d - mx); __syncthreads();
    for (int off = 64; off > 0; off >>= 1) {
        if (j < off) red[j] += red[j + off];
        __syncthreads();
    }
    if (j == 0) g_lse[i] = mx + logf(red[0]);
}

// ---------------- packed 2D FFT (radix-4 DIF) + norms + |Z|^2 ----------------
__global__ __launch_bounds__(1024) void fft_psd_kernel(const float* __restrict__ x1, const float* __restrict__ x2) {
    extern __shared__ float2 sh[];                 // [128][PITCH]
    __shared__ float2 tw[128];
    __shared__ float nb1[32], nb2[32];
    int b = blockIdx.x;
    const float* sa = x1 + (size_t)b*NPIX;
    const float* sb = x2 + (size_t)b*NPIX;
    int tid = threadIdx.x;

    if (tid < 128) {
        float sn, cs;
        sincospif((float)tid / 64.f, &sn, &cs);
        tw[tid] = make_float2(cs, -sn);
    }
    float s1 = 0.f, s2 = 0.f;
    for (int i = tid; i < NPIX; i += 1024) {
        int r = i >> 7, c = i & 127;
        float a = sa[i], bb = sb[i];
        sh[r*PITCH + c] = make_float2(a, bb);
        s1 += a*a; s2 += bb*bb;
    }
#pragma unroll
    for (int o = 16; o; o >>= 1) {
        s1 += __shfl_down_sync(0xffffffffu, s1, o);
        s2 += __shfl_down_sync(0xffffffffu, s2, o);
    }
    if ((tid & 31) == 0) { nb1[tid>>5] = s1; nb2[tid>>5] = s2; }
    __syncthreads();
    if (tid < 32) {
        float a = nb1[tid], c = nb2[tid];
#pragma unroll
        for (int o = 16; o; o >>= 1) {
            a += __shfl_down_sync(0xffffffffu, a, o);
            c += __shfl_down_sync(0xffffffffu, c, o);
        }
        if (tid == 0) { g_norm[b] = a; g_norm[b + BSZ] = c; }
    }

    // ---- rows: pass A (L=128) ----
#pragma unroll
    for (int it = 0; it < 4; it++) {
        int bf = tid + it*1024;
        int row = bf >> 5, j = bf & 31;
        int base = row*PITCH + j;
        float2 u0 = sh[base], u1 = sh[base+32], u2 = sh[base+64], u3 = sh[base+96];
        r4(u0, u1, u2, u3, tw[j], tw[2*j], tw[3*j]);
        sh[base] = u0; sh[base+32] = u1; sh[base+64] = u2; sh[base+96] = u3;
    }
    __syncthreads();
    // ---- rows: pass B (L=32) ----
#pragma unroll
    for (int it = 0; it < 4; it++) {
        int bf = tid + it*1024;
        int row = bf >> 5, t = bf & 31;
        int blk = t >> 3, j = t & 7;
        int base = row*PITCH + blk*32 + j;
        float2 u0 = sh[base], u1 = sh[base+8], u2 = sh[base+16], u3 = sh[base+24];
        r4(u0, u1, u2, u3, tw[4*j], tw[8*j], tw[12*j]);
        sh[base] = u0; sh[base+8] = u1; sh[base+16] = u2; sh[base+24] = u3;
    }
    __syncthreads();
    // ---- rows: pass C (radix-4 L=8 + radix-2) ----
#pragma unroll
    for (int it = 0; it < 2; it++) {
        int g = tid + it*1024;
        int row = g & 127, oct = g >> 7;
        int base = row*PITCH + oct*8;
        float2 v0 = sh[base+0], v1 = sh[base+1], v2 = sh[base+2], v3 = sh[base+3];
        float2 v4 = sh[base+4], v5 = sh[base+5], v6 = sh[base+6], v7 = sh[base+7];
        r4nw(v0, v2, v4, v6);
        r4(v1, v3, v5, v7, tw[16], tw[32], tw[48]);
        r2(v0, v1); r2(v2, v3); r2(v4, v5); r2(v6, v7);
        sh[base+0] = v0; sh[base+1] = v1; sh[base+2] = v2; sh[base+3] = v3;
        sh[base+4] = v4; sh[base+5] = v5; sh[base+6] = v6; sh[base+7] = v7;
    }
    __syncthreads();

    // ---- cols: pass A ----
#pragma unroll
    for (int it = 0; it < 4; it++) {
        int bf = tid + it*1024;
        int col = bf & 127, j = bf >> 7;
        int base = j*PITCH + col;
        float2 u0 = sh[base], u1 = sh[base+32*PITCH], u2 = sh[base+64*PITCH], u3 = sh[base+96*PITCH];
        r4(u0, u1, u2, u3, tw[j], tw[2*j], tw[3*j]);
        sh[base] = u0; sh[base+32*PITCH] = u1; sh[base+64*PITCH] = u2; sh[base+96*PITCH] = u3;
    }
    __syncthreads();
    // ---- cols: pass B ----
#pragma unroll
    for (int it = 0; it < 4; it++) {
        int bf = tid + it*1024;
        int col = bf & 127, t = bf >> 7;
        int blk = t >> 3, j = t & 7;
        int base = (blk*32 + j)*PITCH + col;
        float2 u0 = sh[base], u1 = sh[base+8*PITCH], u2 = sh[base+16*PITCH], u3 = sh[base+24*PITCH];
        r4(u0, u1, u2, u3, tw[4*j], tw[8*j], tw[12*j]);
        sh[base] = u0; sh[base+8*PITCH] = u1; sh[base+16*PITCH] = u2; sh[base+24*PITCH] = u3;
    }
    __syncthreads();
    // ---- cols: pass C ----
#pragma unroll
    for (int it = 0; it < 2; it++) {
        int g = tid + it*1024;
        int col = g & 127, oct = g >> 7;
        int base = (oct*8)*PITCH + col;
        float2 v0 = sh[base+0*PITCH], v1 = sh[base+1*PITCH], v2 = sh[base+2*PITCH], v3 = sh[base+3*PITCH];
        float2 v4 = sh[base+4*PITCH], v5 = sh[base+5*PITCH], v6 = sh[base+6*PITCH], v7 = sh[base+7*PITCH];
        r4nw(v0, v2, v4, v6);
        r4(v1, v3, v5, v7, tw[16], tw[32], tw[48]);
        r2(v0, v1); r2(v2, v3); r2(v4, v5); r2(v6, v7);
        sh[base+0*PITCH] = v0; sh[base+1*PITCH] = v1; sh[base+2*PITCH] = v2; sh[base+3*PITCH] = v3;
        sh[base+4*PITCH] = v4; sh[base+5*PITCH] = v5; sh[base+6*PITCH] = v6; sh[base+7*PITCH] = v7;
    }
    __syncthreads();

    for (int i = tid; i < NPIX; i += 1024) {
        int r = i >> 7, c = i & 127;
        float2 v = sh[r*PITCH + c];
        g_psd[(size_t)b*NPIX + i] = v.x*v.x + v.y*v.y;
    }
}

// ---------------- S partials: 8 image-groups in parallel, float4 ----------------
__global__ void psd_reduce_kernel() {
    int t = blockIdx.x * 128 + threadIdx.x;        // quad index 0..4095
    int imgbase = blockIdx.y * 16;
    const float4* src = reinterpret_cast<const float4*>(g_psd);
    float4 s = make_float4(0.f, 0.f, 0.f, 0.f);
#pragma unroll
    for (int i = 0; i < 16; i++) {
        float4 v = src[(size_t)(imgbase + i)*(NPIX/4) + t];
        s.x += v.x; s.y += v.y; s.z += v.z; s.w += v.w;
    }
    reinterpret_cast<float4*>(g_S)[(size_t)blockIdx.y*(NPIX/4) + t] = s;
}

// ---------------- per-bin avgpsd via -k pairing, float log, 128 CTAs ----------------
__global__ void psd_stats_kernel() {
    int p = blockIdx.x * 128 + threadIdx.x;
    int pr = p >> 7, pc = p & 127;
    int q = tau(pr) * 128 + tau(pc);
    double Sp = 0.0, Sq = 0.0;
#pragma unroll
    for (int h = 0; h < 8; h++) { Sp += (double)g_S[h*NPIX + p]; Sq += (double)g_S[h*NPIX + q]; }
    double avg = (Sp + Sq) * (1.0 / 512.0);
    __shared__ double shl[128];
    __shared__ double sha[128];
    shl[threadIdx.x] = (double)logf((float)avg);
    sha[threadIdx.x] = avg;
    __syncthreads();
    for (int off = 64; off > 0; off >>= 1) {
        if (threadIdx.x < off) {
            shl[threadIdx.x] += shl[threadIdx.x + off];
            sha[threadIdx.x] += sha[threadIdx.x + off];
        }
        __syncthreads();
    }
    if (threadIdx.x == 0) { g_red_log[blockIdx.x] = shl[0]; g_red_avg[blockIdx.x] = sha[0]; }
}

// ---------------- final scalar ----------------
__global__ void final_kernel(float* __restrict__ out) {
    __shared__ double sh[128];
    int t = threadIdx.x;

    sh[t] = (double)(g_lse[t] - g_dist[t*BSZ + t]);
    __syncthreads();
    for (int off = 64; off > 0; off >>= 1) {
        if (t < off) sh[t] += sh[t + off];
        __syncthreads();
    }
    double ce = sh[0] / (double)BSZ;
    __syncthreads();

    sh[t] = g_red_log[t]; __syncthreads();
    for (int off = 64; off > 0; off >>= 1) {
        if (t < off) sh[t] += sh[t + off];
        __syncthreads();
    }
    double slog = sh[0];
    __syncthreads();

    sh[t] = g_red_avg[t]; __syncthreads();
    for (int off = 64; off > 0; off >>= 1) {
        if (t < off) sh[t] += sh[t + off];
        __syncthreads();
    }
    double savg = sh[0];

    if (t == 0) {
        double r = slog / (double)NPIX - log(savg / (double)NPIX);
        out[0] = (float)(ce - 0.1 * r);
    }
}

// ---------------- launch ----------------
extern "C" void kernel_launch(void* const* d_in, const int* in_sizes, int n_in,
                              void* d_out, int out_size) {
    const float* x1 = (const float*)d_in[0];
    const float* x2 = (const float*)d_in[1];
    float* out = (float*)d_out;

    const int smem = HW * PITCH * (int)sizeof(float2);   // 132096 B
    cudaFuncSetAttribute(fft_psd_kernel, cudaFuncAttributeMaxDynamicSharedMemorySize, smem);

    fft_psd_kernel<<<NPACK, 1024, smem>>>(x1, x2);
    dot_kernel<<<dim3(2, 1, GK), 256>>>(x1, x2);
    dist_lse_kernel<<<BSZ, BSZ>>>();
    psd_reduce_kernel<<<dim3(32, 8), 128>>>();
    psd_stats_kernel<<<128, 128>>>();
    final_kernel<<<1, 128>>>(out);
}

// round 7
// speedup vs baseline: 4.3031x; 1.1174x over previous
#include <cuda_runtime.h>
#include <math.h>

#define HW     128
#define NPIX   (HW*HW)        // 16384
#define BSZ    128
#define NPACK  128            // packed complex images
#define PITCHF 129            // smem row pitch in floats (odd => row+const bank maps)
#define GK     64             // GEMM K-splits (chunk = 256)
#define NGRP   16             // psd reduction image groups

// ---------------- device scratch ----------------
__device__ float  g_norm[2*BSZ];
__device__ float  g_dot_part[GK*BSZ*BSZ];         // 4 MB partial dots
__device__ float  g_dist[BSZ*BSZ];
__device__ float  g_lse[BSZ];
__device__ float  g_psd[NPACK*NPIX];              // per packed-image |Z|^2 (8 MB)
__device__ float  g_S[NGRP*NPIX];                 // image-group partial sums
__device__ double g_red_log[128];
__device__ double g_red_avg[128];

// ---------------- f32x2 packed helpers ----------------
__device__ __forceinline__ unsigned long long pk2(float x){
    unsigned long long r; asm("mov.b64 %0, {%1, %1};" : "=l"(r) : "f"(x)); return r;
}
__device__ __forceinline__ void upk2(unsigned long long v, float& lo, float& hi){
    asm("mov.b64 {%0, %1}, %2;" : "=f"(lo), "=f"(hi) : "l"(v));
}
__device__ __forceinline__ void ffma2(unsigned long long& c, unsigned long long a, unsigned long long b){
    asm("fma.rn.f32x2 %0, %1, %2, %3;" : "=l"(c) : "l"(a), "l"(b), "l"(c));
}

// ---------------- complex helpers (separate re/im) ----------------
__device__ __forceinline__ void cmulw(float& vr, float& vi, float2 w){
    float t = vr;
    vr = vr*w.x - vi*w.y;
    vi = t*w.y + vi*w.x;
}
// radix-4 DIF butterfly with twiddles on u1..u3
__device__ __forceinline__ void r4s(float&u0r,float&u0i,float&u1r,float&u1i,
                                    float&u2r,float&u2i,float&u3r,float&u3i,
                                    float2 w1, float2 w2, float2 w3){
    float t0r=u0r+u2r, t0i=u0i+u2i, t1r=u0r-u2r, t1i=u0i-u2i;
    float t2r=u1r+u3r, t2i=u1i+u3i, t3r=u1r-u3r, t3i=u1i-u3i;
    float m3r=t3i, m3i=-t3r;                      // -i*t3
    u0r=t0r+t2r; u0i=t0i+t2i;
    u1r=t1r+m3r; u1i=t1i+m3i; cmulw(u1r,u1i,w1);
    u2r=t0r-t2r; u2i=t0i-t2i; cmulw(u2r,u2i,w2);
    u3r=t1r-m3r; u3i=t1i-m3i; cmulw(u3r,u3i,w3);
}
__device__ __forceinline__ void r4nws(float&u0r,float&u0i,float&u1r,float&u1i,
                                      float&u2r,float&u2i,float&u3r,float&u3i){
    float t0r=u0r+u2r, t0i=u0i+u2i, t1r=u0r-u2r, t1i=u0i-u2i;
    float t2r=u1r+u3r, t2i=u1i+u3i, t3r=u1r-u3r, t3i=u1i-u3i;
    float m3r=t3i, m3i=-t3r;
    u0r=t0r+t2r; u0i=t0i+t2i;
    u1r=t1r+m3r; u1i=t1i+m3i;
    u2r=t0r-t2r; u2i=t0i-t2i;
    u3r=t1r-m3r; u3i=t1i-m3i;
}
__device__ __forceinline__ void r2s(float&ar,float&ai,float&br,float&bi){
    float sr=ar+br, si=ai+bi, dr=ar-br, di=ai-bi;
    ar=sr; ai=si; br=dr; bi=di;
}

// DIF digit-reversal permutation for stage order (radix 4,4,4,2):
__device__ __forceinline__ int sigp(int p){
    return (p>>5) + (((p>>3)&3)<<2) + (((p>>1)&3)<<4) + ((p&1)<<6);
}
__device__ __forceinline__ int isigp(int k){
    return ((k&3)<<5) + (((k>>2)&3)<<3) + (((k>>4)&3)<<1) + (k>>6);
}
__device__ __forceinline__ int tau(int p){
    return isigp((128 - sigp(p)) & 127);
}

// ---------------- GEMM: dot(a_i, b_j), f32x2 packed, K-split 64 ----------------
__global__ __launch_bounds__(256) void dot_kernel(const float* __restrict__ A, const float* __restrict__ B) {
    __shared__ __align__(16) float As[16][132];
    __shared__ __align__(16) float Bs[16][68];
    int tid = threadIdx.x;
    int tx = tid & 15, ty = tid >> 4;
    int nb = blockIdx.x * 64;
    int k0 = blockIdx.z * 256;

    unsigned long long acc[4][4];
#pragma unroll
    for (int rp = 0; rp < 4; rp++)
#pragma unroll
        for (int c = 0; c < 4; c++) acc[rp][c] = 0ull;

    for (int ks = 0; ks < 16; ks++) {
        int kb = k0 + ks * 16;
        __syncthreads();
#pragma unroll
        for (int i = 0; i < 2; i++) {
            int idx = tid + i * 256;
            int row = idx >> 2, kq = idx & 3;
            float4 v = *reinterpret_cast<const float4*>(A + (size_t)row * NPIX + kb + kq * 4);
            As[kq*4+0][row] = v.x; As[kq*4+1][row] = v.y;
            As[kq*4+2][row] = v.z; As[kq*4+3][row] = v.w;
        }
        {
            int row = tid >> 2, kq = tid & 3;
            float4 v = *reinterpret_cast<const float4*>(B + (size_t)(nb + row) * NPIX + kb + kq * 4);
            Bs[kq*4+0][row] = v.x; Bs[kq*4+1][row] = v.y;
            Bs[kq*4+2][row] = v.z; Bs[kq*4+3][row] = v.w;
        }
        __syncthreads();
#pragma unroll
        for (int kk = 0; kk < 16; kk++) {
            const double2* ap = reinterpret_cast<const double2*>(&As[kk][ty*8]);
            double2 a01 = ap[0], a23 = ap[1];
            unsigned long long a2[4];
            a2[0] = __double_as_longlong(a01.x);
            a2[1] = __double_as_longlong(a01.y);
            a2[2] = __double_as_longlong(a23.x);
            a2[3] = __double_as_longlong(a23.y);
            float4 b0 = *reinterpret_cast<const float4*>(&Bs[kk][tx*4]);
            unsigned long long b2[4];
            b2[0] = pk2(b0.x); b2[1] = pk2(b0.y); b2[2] = pk2(b0.z); b2[3] = pk2(b0.w);
#pragma unroll
            for (int rp = 0; rp < 4; rp++)
#pragma unroll
                for (int c = 0; c < 4; c++) ffma2(acc[rp][c], a2[rp], b2[c]);
        }
    }
    float* outp = g_dot_part + (size_t)blockIdx.z * BSZ * BSZ;
#pragma unroll
    for (int rp = 0; rp < 4; rp++) {
        float lo0, hi0, lo1, hi1, lo2, hi2, lo3, hi3;
        upk2(acc[rp][0], lo0, hi0); upk2(acc[rp][1], lo1, hi1);
        upk2(acc[rp][2], lo2, hi2); upk2(acc[rp][3], lo3, hi3);
        *reinterpret_cast<float4*>(outp + (ty*8 + 2*rp    ) * BSZ + nb + tx*4) = make_float4(lo0, lo1, lo2, lo3);
        *reinterpret_cast<float4*>(outp + (ty*8 + 2*rp + 1) * BSZ + nb + tx*4) = make_float4(hi0, hi1, hi2, hi3);
    }
}

// ---------------- Dist + per-row logsumexp ----------------
__global__ void dist_lse_kernel() {
    int i = blockIdx.x, j = threadIdx.x;
    float dot = 0.f;
#pragma unroll 16
    for (int s = 0; s < GK; s++) dot += g_dot_part[(size_t)s*BSZ*BSZ + i*BSZ + j];
    float d2 = g_norm[i] + g_norm[BSZ + j] - 2.f * dot;
    float d = sqrtf(fmaxf(d2, 0.f));
    g_dist[i*BSZ + j] = d;

    __shared__ float red[BSZ];
    red[j] = d; __syncthreads();
    for (int off = 64; off > 0; off >>= 1) {
        if (j < off) red[j] = fmaxf(red[j], red[j + off]);
        __syncthreads();
    }
    float mx = red[0]; __syncthreads();
    red[j] = expf(d - mx); __syncthreads();
    for (int off = 64; off > 0; off >>= 1) {
        if (j < off) red[j] += red[j + off];
        __syncthreads();
    }
    if (j == 0) g_lse[i] = mx + logf(red[0]);
}

// ---------------- packed 2D FFT (radix-4 DIF, conflict-free) + norms + |Z|^2 ----------------
__global__ __launch_bounds__(1024) void fft_psd_kernel(const float* __restrict__ x1, const float* __restrict__ x2) {
    extern __shared__ float sm[];
    float* SRe = sm;                               // [128][PITCHF]
    float* SIm = sm + 128*PITCHF;
    __shared__ float2 tw[128];
    __shared__ float nb1[32], nb2[32];
    int b = blockIdx.x;
    const float* sa = x1 + (size_t)b*NPIX;
    const float* sb = x2 + (size_t)b*NPIX;
    int tid = threadIdx.x;

    if (tid < 128) {
        float sn, cs;
        sincospif((float)tid / 64.f, &sn, &cs);
        tw[tid] = make_float2(cs, -sn);            // W128^tid
    }
    float s1 = 0.f, s2 = 0.f;
    for (int i = tid; i < NPIX; i += 1024) {
        int r = i >> 7, c = i & 127;
        float a = sa[i], bb = sb[i];
        SRe[r*PITCHF + c] = a;
        SIm[r*PITCHF + c] = bb;
        s1 += a*a; s2 += bb*bb;
    }
#pragma unroll
    for (int o = 16; o; o >>= 1) {
        s1 += __shfl_down_sync(0xffffffffu, s1, o);
        s2 += __shfl_down_sync(0xffffffffu, s2, o);
    }
    if ((tid & 31) == 0) { nb1[tid>>5] = s1; nb2[tid>>5] = s2; }
    __syncthreads();
    if (tid < 32) {
        float a = nb1[tid], c = nb2[tid];
#pragma unroll
        for (int o = 16; o; o >>= 1) {
            a += __shfl_down_sync(0xffffffffu, a, o);
            c += __shfl_down_sync(0xffffffffu, c, o);
        }
        if (tid == 0) { g_norm[b] = a; g_norm[b + BSZ] = c; }
    }
    __syncthreads();

    // ---- rows pass A (L=128): warp = 32 j's in one row; banks row+j distinct ----
#pragma unroll
    for (int it = 0; it < 4; it++) {
        int bf = tid + it*1024;
        int row = bf >> 5, j = bf & 31;
        int base = row*PITCHF + j;
        float u0r=SRe[base],    u0i=SIm[base];
        float u1r=SRe[base+32], u1i=SIm[base+32];
        float u2r=SRe[base+64], u2i=SIm[base+64];
        float u3r=SRe[base+96], u3i=SIm[base+96];
        r4s(u0r,u0i,u1r,u1i,u2r,u2i,u3r,u3i, tw[j], tw[2*j], tw[3*j]);
        SRe[base]=u0r;    SIm[base]=u0i;
        SRe[base+32]=u1r; SIm[base+32]=u1i;
        SRe[base+64]=u2r; SIm[base+64]=u2i;
        SRe[base+96]=u3r; SIm[base+96]=u3i;
    }
    __syncthreads();
    // ---- rows pass B (L=32): lane = rr*8+j, rows strided by 8 -> banks rr*8+j+g1 ----
#pragma unroll
    for (int it = 0; it < 4; it++) {
        int lane = tid & 31;
        int rr = lane >> 3, j = lane & 7;
        int wt = it*32 + (tid >> 5);               // 0..127
        int blk = wt & 3, g1 = (wt >> 2) & 7, g0 = wt >> 5;
        int row = g0*32 + rr*8 + g1;
        int base = row*PITCHF + blk*32 + j;
        float u0r=SRe[base],    u0i=SIm[base];
        float u1r=SRe[base+8],  u1i=SIm[base+8];
        float u2r=SRe[base+16], u2i=SIm[base+16];
        float u3r=SRe[base+24], u3i=SIm[base+24];
        r4s(u0r,u0i,u1r,u1i,u2r,u2i,u3r,u3i, tw[4*j], tw[8*j], tw[12*j]);
        SRe[base]=u0r;    SIm[base]=u0i;
        SRe[base+8]=u1r;  SIm[base+8]=u1i;
        SRe[base+16]=u2r; SIm[base+16]=u2i;
        SRe[base+24]=u3r; SIm[base+24]=u3i;
    }
    __syncthreads();
    // ---- rows pass C (radix-4 L=8 + radix-2): warp = 32 consecutive rows ----
#pragma unroll
    for (int it = 0; it < 2; it++) {
        int g = tid + it*1024;
        int row = g & 127, oct = g >> 7;
        int base = row*PITCHF + oct*8;
        float v0r=SRe[base+0], v0i=SIm[base+0], v1r=SRe[base+1], v1i=SIm[base+1];
        float v2r=SRe[base+2], v2i=SIm[base+2], v3r=SRe[base+3], v3i=SIm[base+3];
        float v4r=SRe[base+4], v4i=SIm[base+4], v5r=SRe[base+5], v5i=SIm[base+5];
        float v6r=SRe[base+6], v6i=SIm[base+6], v7r=SRe[base+7], v7i=SIm[base+7];
        r4nws(v0r,v0i, v2r,v2i, v4r,v4i, v6r,v6i);
        r4s(v1r,v1i, v3r,v3i, v5r,v5i, v7r,v7i, tw[16], tw[32], tw[48]);
        r2s(v0r,v0i, v1r,v1i); r2s(v2r,v2i, v3r,v3i);
        r2s(v4r,v4i, v5r,v5i); r2s(v6r,v6i, v7r,v7i);
        SRe[base+0]=v0r; SIm[base+0]=v0i; SRe[base+1]=v1r; SIm[base+1]=v1i;
        SRe[base+2]=v2r; SIm[base+2]=v2i; SRe[base+3]=v3r; SIm[base+3]=v3i;
        SRe[base+4]=v4r; SIm[base+4]=v4i; SRe[base+5]=v5r; SIm[base+5]=v5i;
        SRe[base+6]=v6r; SIm[base+6]=v6i; SRe[base+7]=v7r; SIm[base+7]=v7i;
    }
    __syncthreads();

    // ---- cols pass A: warp = 32 consecutive cols ----
#pragma unroll
    for (int it = 0; it < 4; it++) {
        int bf = tid + it*1024;
        int col = bf & 127, j = bf >> 7;
        int base = j*PITCHF + col;
        float u0r=SRe[base],           u0i=SIm[base];
        float u1r=SRe[base+32*PITCHF], u1i=SIm[base+32*PITCHF];
        float u2r=SRe[base+64*PITCHF], u2i=SIm[base+64*PITCHF];
        float u3r=SRe[base+96*PITCHF], u3i=SIm[base+96*PITCHF];
        r4s(u0r,u0i,u1r,u1i,u2r,u2i,u3r,u3i, tw[j], tw[2*j], tw[3*j]);
        SRe[base]=u0r;           SIm[base]=u0i;
        SRe[base+32*PITCHF]=u1r; SIm[base+32*PITCHF]=u1i;
        SRe[base+64*PITCHF]=u2r; SIm[base+64*PITCHF]=u2i;
        SRe[base+96*PITCHF]=u3r; SIm[base+96*PITCHF]=u3i;
    }
    __syncthreads();
    // ---- cols pass B ----
#pragma unroll
    for (int it = 0; it < 4; it++) {
        int bf = tid + it*1024;
        int col = bf & 127, t = bf >> 7;
        int blk = t >> 3, j = t & 7;
        int base = (blk*32 + j)*PITCHF + col;
        float u0r=SRe[base],           u0i=SIm[base];
        float u1r=SRe[base+8*PITCHF],  u1i=SIm[base+8*PITCHF];
        float u2r=SRe[base+16*PITCHF], u2i=SIm[base+16*PITCHF];
        float u3r=SRe[base+24*PITCHF], u3i=SIm[base+24*PITCHF];
        r4s(u0r,u0i,u1r,u1i,u2r,u2i,u3r,u3i, tw[4*j], tw[8*j], tw[12*j]);
        SRe[base]=u0r;           SIm[base]=u0i;
        SRe[base+8*PITCHF]=u1r;  SIm[base+8*PITCHF]=u1i;
        SRe[base+16*PITCHF]=u2r; SIm[base+16*PITCHF]=u2i;
        SRe[base+24*PITCHF]=u3r; SIm[base+24*PITCHF]=u3i;
    }
    __syncthreads();
    // ---- cols pass C ----
#pragma unroll
    for (int it = 0; it < 2; it++) {
        int g = tid + it*1024;
        int col = g & 127, oct = g >> 7;
        int base = (oct*8)*PITCHF + col;
        float v0r=SRe[base+0*PITCHF], v0i=SIm[base+0*PITCHF], v1r=SRe[base+1*PITCHF], v1i=SIm[base+1*PITCHF];
        float v2r=SRe[base+2*PITCHF], v2i=SIm[base+2*PITCHF], v3r=SRe[base+3*PITCHF], v3i=SIm[base+3*PITCHF];
        float v4r=SRe[base+4*PITCHF], v4i=SIm[base+4*PITCHF], v5r=SRe[base+5*PITCHF], v5i=SIm[base+5*PITCHF];
        float v6r=SRe[base+6*PITCHF], v6i=SIm[base+6*PITCHF], v7r=SRe[base+7*PITCHF], v7i=SIm[base+7*PITCHF];
        r4nws(v0r,v0i, v2r,v2i, v4r,v4i, v6r,v6i);
        r4s(v1r,v1i, v3r,v3i, v5r,v5i, v7r,v7i, tw[16], tw[32], tw[48]);
        r2s(v0r,v0i, v1r,v1i); r2s(v2r,v2i, v3r,v3i);
        r2s(v4r,v4i, v5r,v5i); r2s(v6r,v6i, v7r,v7i);
        SRe[base+0*PITCHF]=v0r; SIm[base+0*PITCHF]=v0i; SRe[base+1*PITCHF]=v1r; SIm[base+1*PITCHF]=v1i;
        SRe[base+2*PITCHF]=v2r; SIm[base+2*PITCHF]=v2i; SRe[base+3*PITCHF]=v3r; SIm[base+3*PITCHF]=v3i;
        SRe[base+4*PITCHF]=v4r; SIm[base+4*PITCHF]=v4i; SRe[base+5*PITCHF]=v5r; SIm[base+5*PITCHF]=v5i;
        SRe[base+6*PITCHF]=v6r; SIm[base+6*PITCHF]=v6i; SRe[base+7*PITCHF]=v7r; SIm[base+7*PITCHF]=v7i;
    }
    __syncthreads();

    for (int i = tid; i < NPIX; i += 1024) {
        int r = i >> 7, c = i & 127;
        float vr = SRe[r*PITCHF + c], vi = SIm[r*PITCHF + c];
        g_psd[(size_t)b*NPIX + i] = vr*vr + vi*vi;
    }
}

// ---------------- S partials: 16 image-groups in parallel, float4 ----------------
__global__ void psd_reduce_kernel() {
    int t = blockIdx.x * 128 + threadIdx.x;        // quad index 0..4095
    int imgbase = blockIdx.y * 8;
    const float4* src = reinterpret_cast<const float4*>(g_psd);
    float4 s = make_float4(0.f, 0.f, 0.f, 0.f);
#pragma unroll
    for (int i = 0; i < 8; i++) {
        float4 v = src[(size_t)(imgbase + i)*(NPIX/4) + t];
        s.x += v.x; s.y += v.y; s.z += v.z; s.w += v.w;
    }
    reinterpret_cast<float4*>(g_S)[(size_t)blockIdx.y*(NPIX/4) + t] = s;
}

// ---------------- per-bin avgpsd via -k pairing, float log, 128 CTAs ----------------
__global__ void psd_stats_kernel() {
    int p = blockIdx.x * 128 + threadIdx.x;
    int pr = p >> 7, pc = p & 127;
    int q = tau(pr) * 128 + tau(pc);
    double Sp = 0.0, Sq = 0.0;
#pragma unroll
    for (int h = 0; h < NGRP; h++) { Sp += (double)g_S[h*NPIX + p]; Sq += (double)g_S[h*NPIX + q]; }
    double avg = (Sp + Sq) * (1.0 / 512.0);
    __shared__ double shl[128];
    __shared__ double sha[128];
    shl[threadIdx.x] = (double)logf((float)avg);
    sha[threadIdx.x] = avg;
    __syncthreads();
    for (int off = 64; off > 0; off >>= 1) {
        if (threadIdx.x < off) {
            shl[threadIdx.x] += shl[threadIdx.x + off];
            sha[threadIdx.x] += sha[threadIdx.x + off];
        }
        __syncthreads();
    }
    if (threadIdx.x == 0) { g_red_log[blockIdx.x] = shl[0]; g_red_avg[blockIdx.x] = sha[0]; }
}

// ---------------- final scalar ----------------
__global__ void final_kernel(float* __restrict__ out) {
    __shared__ double sh[128];
    int t = threadIdx.x;

    sh[t] = (double)(g_lse[t] - g_dist[t*BSZ + t]);
    __syncthreads();
    for (int off = 64; off > 0; off >>= 1) {
        if (t < off) sh[t] += sh[t + off];
        __syncthreads();
    }
    double ce = sh[0] / (double)BSZ;
    __syncthreads();

    sh[t] = g_red_log[t]; __syncthreads();
    for (int off = 64; off > 0; off >>= 1) {
        if (t < off) sh[t] += sh[t + off];
        __syncthreads();
    }
    double slog = sh[0];
    __syncthreads();

    sh[t] = g_red_avg[t]; __syncthreads();
    for (int off = 64; off > 0; off >>= 1) {
        if (t < off) sh[t] += sh[t + off];
        __syncthreads();
    }
    double savg = sh[0];

    if (t == 0) {
        double r = slog / (double)NPIX - log(savg / (double)NPIX);
        out[0] = (float)(ce - 0.1 * r);
    }
}

// ---------------- launch ----------------
extern "C" void kernel_launch(void* const* d_in, const int* in_sizes, int n_in,
                              void* d_out, int out_size) {
    const float* x1 = (const float*)d_in[0];
    const float* x2 = (const float*)d_in[1];
    float* out = (float*)d_out;

    const int smem = 2 * 128 * PITCHF * (int)sizeof(float);   // 132096 B
    cudaFuncSetAttribute(fft_psd_kernel, cudaFuncAttributeMaxDynamicSharedMemorySize, smem);

    fft_psd_kernel<<<NPACK, 1024, smem>>>(x1, x2);
    dot_kernel<<<dim3(2, 1, GK), 256>>>(x1, x2);
    dist_lse_kernel<<<BSZ, BSZ>>>();
    psd_reduce_kernel<<<dim3(32, NGRP), 128>>>();
    psd_stats_kernel<<<128, 128>>>();
    final_kernel<<<1, 128>>>(out);
}

// round 9
// speedup vs baseline: 4.3843x; 1.0189x over previous
#include <cuda_runtime.h>
#include <math.h>

#define HW     128
#define NPIX   (HW*HW)        // 16384
#define BSZ    128
#define NPACK  128            // packed complex images
#define PITCHF 129            // smem row pitch in floats
#define GK     64             // GEMM K-splits (chunk = 256)
#define NGRP   32             // psd reduction image groups

// ---------------- device scratch ----------------
__device__ float  g_norm[2*BSZ];
__device__ float  g_dot_part[GK*BSZ*BSZ];         // 4 MB partial dots
__device__ float  g_dist[BSZ*BSZ];
__device__ float  g_lse[BSZ];
__device__ float  g_psd[NPACK*NPIX];              // per packed-image |Z|^2 (8 MB)
__device__ float  g_S[NGRP*NPIX];                 // image-group partial sums (2 MB)
__device__ double g_red_log[128];
__device__ double g_red_avg[128];

// ---------------- f32x2 packed helpers ----------------
__device__ __forceinline__ unsigned long long pk2(float x){
    unsigned long long r; asm("mov.b64 %0, {%1, %1};" : "=l"(r) : "f"(x)); return r;
}
__device__ __forceinline__ void upk2(unsigned long long v, float& lo, float& hi){
    asm("mov.b64 {%0, %1}, %2;" : "=f"(lo), "=f"(hi) : "l"(v));
}
__device__ __forceinline__ void ffma2(unsigned long long& c, unsigned long long a, unsigned long long b){
    asm("fma.rn.f32x2 %0, %1, %2, %3;" : "=l"(c) : "l"(a), "l"(b), "l"(c));
}

// ---------------- FFT register helpers ----------------
__device__ __forceinline__ void cmul_ip(float& vr, float& vi, float2 w){
    float t = vr;
    vr = vr*w.x - vi*w.y;
    vi = t*w.y + vi*w.x;
}
__device__ __forceinline__ void bf4(float&x0r,float&x0i,float&x1r,float&x1i,
                                    float&x2r,float&x2i,float&x3r,float&x3i){
    float t0r=x0r+x2r, t0i=x0i+x2i, t1r=x0r-x2r, t1i=x0i-x2i;
    float t2r=x1r+x3r, t2i=x1i+x3i, t3r=x1r-x3r, t3i=x1i-x3i;
    x0r=t0r+t2r; x0i=t0i+t2i;
    x1r=t1r+t3i; x1i=t1i-t3r;     // t1 + (-i)*t3
    x2r=t0r-t2r; x2i=t0i-t2i;
    x3r=t1r-t3i; x3i=t1i+t3r;     // t1 + (+i)*t3
}

// 16-pt DFT (DIF radix-4 x radix-4). Natural in; slot (4e1+e2) holds d = e1+4e2.
__device__ __forceinline__ void fft16(float* xr, float* xi, const float2* tw){
#pragma unroll
    for (int s0 = 0; s0 < 4; s0++){
        bf4(xr[s0],xi[s0], xr[s0+4],xi[s0+4], xr[s0+8],xi[s0+8], xr[s0+12],xi[s0+12]);
        if (s0){
            cmul_ip(xr[s0+4],  xi[s0+4],  tw[8*s0]);
            cmul_ip(xr[s0+8],  xi[s0+8],  tw[16*s0]);
            cmul_ip(xr[s0+12], xi[s0+12], tw[24*s0]);
        }
    }
#pragma unroll
    for (int e1 = 0; e1 < 4; e1++)
        bf4(xr[4*e1],xi[4*e1], xr[4*e1+1],xi[4*e1+1],
            xr[4*e1+2],xi[4*e1+2], xr[4*e1+3],xi[4*e1+3]);
}

// 8-pt DFT (DIF radix-2 x radix-4). Natural in; slot (4f1+f2) holds k' = f1+2f2.
__device__ __forceinline__ void fft8(float* yr, float* yi, const float2* tw){
#pragma unroll
    for (int n2 = 0; n2 < 4; n2++){
        float ur=yr[n2], ui=yi[n2], vr=yr[n2+4], vi=yi[n2+4];
        yr[n2]=ur+vr; yi[n2]=ui+vi;
        float dr=ur-vr, di=ui-vi;
        if (n2 == 0){ yr[n2+4]=dr; yi[n2+4]=di; }
        else {
            float2 w = tw[16*n2];                       // W8^{n2}
            yr[n2+4]=dr*w.x-di*w.y; yi[n2+4]=dr*w.y+di*w.x;
        }
    }
    bf4(yr[0],yi[0], yr[1],yi[1], yr[2],yi[2], yr[3],yi[3]);
    bf4(yr[4],yi[4], yr[5],yi[5], yr[6],yi[6], yr[7],yi[7]);
}

// stored index p = 8*d1 + k'  ->  frequency k = d1 + 16*k'
__device__ __forceinline__ int sig2(int p){ return (p>>3) | ((p&7)<<4); }
__device__ __forceinline__ int isig2(int k){ return ((k&15)<<3) | (k>>4); }
__device__ __forceinline__ int tau2(int p){ return isig2((128 - sig2(p)) & 127); }

// ---------------- GEMM: dot(a_i, b_j), f32x2 packed, K-split 64 ----------------
__global__ __launch_bounds__(256) void dot_kernel(const float* __restrict__ A, const float* __restrict__ B) {
    __shared__ __align__(16) float As[16][132];
    __shared__ __align__(16) float Bs[16][68];
    int tid = threadIdx.x;
    int tx = tid & 15, ty = tid >> 4;
    int nb = blockIdx.x * 64;
    int k0 = blockIdx.z * 256;

    unsigned long long acc[4][4];
#pragma unroll
    for (int rp = 0; rp < 4; rp++)
#pragma unroll
        for (int c = 0; c < 4; c++) acc[rp][c] = 0ull;

    for (int ks = 0; ks < 16; ks++) {
        int kb = k0 + ks * 16;
        __syncthreads();
#pragma unroll
        for (int i = 0; i < 2; i++) {
            int idx = tid + i * 256;
            int row = idx >> 2, kq = idx & 3;
            float4 v = *reinterpret_cast<const float4*>(A + (size_t)row * NPIX + kb + kq * 4);
            As[kq*4+0][row] = v.x; As[kq*4+1][row] = v.y;
            As[kq*4+2][row] = v.z; As[kq*4+3][row] = v.w;
        }
        {
            int row = tid >> 2, kq = tid & 3;
            float4 v = *reinterpret_cast<const float4*>(B + (size_t)(nb + row) * NPIX + kb + kq * 4);
            Bs[kq*4+0][row] = v.x; Bs[kq*4+1][row] = v.y;
            Bs[kq*4+2][row] = v.z; Bs[kq*4+3][row] = v.w;
        }
        __syncthreads();
#pragma unroll
        for (int kk = 0; kk < 16; kk++) {
            const double2* ap = reinterpret_cast<const double2*>(&As[kk][ty*8]);
            double2 a01 = ap[0], a23 = ap[1];
            unsigned long long a2[4];
            a2[0] = __double_as_longlong(a01.x);
            a2[1] = __double_as_longlong(a01.y);
            a2[2] = __double_as_longlong(a23.x);
            a2[3] = __double_as_longlong(a23.y);
            float4 b0 = *reinterpret_cast<const float4*>(&Bs[kk][tx*4]);
            unsigned long long b2[4];
            b2[0] = pk2(b0.x); b2[1] = pk2(b0.y); b2[2] = pk2(b0.z); b2[3] = pk2(b0.w);
#pragma unroll
            for (int rp = 0; rp < 4; rp++)
#pragma unroll
                for (int c = 0; c < 4; c++) ffma2(acc[rp][c], a2[rp], b2[c]);
        }
    }
    float* outp = g_dot_part + (size_t)blockIdx.z * BSZ * BSZ;
#pragma unroll
    for (int rp = 0; rp < 4; rp++) {
        float lo0, hi0, lo1, hi1, lo2, hi2, lo3, hi3;
        upk2(acc[rp][0], lo0, hi0); upk2(acc[rp][1], lo1, hi1);
        upk2(acc[rp][2], lo2, hi2); upk2(acc[rp][3], lo3, hi3);
        *reinterpret_cast<float4*>(outp + (ty*8 + 2*rp    ) * BSZ + nb + tx*4) = make_float4(lo0, lo1, lo2, lo3);
        *reinterpret_cast<float4*>(outp + (ty*8 + 2*rp + 1) * BSZ + nb + tx*4) = make_float4(hi0, hi1, hi2, hi3);
    }
}

// ---------------- Dist + per-row logsumexp ----------------
__global__ void dist_lse_kernel() {
    int i = blockIdx.x, j = threadIdx.x;
    float dot = 0.f;
#pragma unroll 16
    for (int s = 0; s < GK; s++) dot += g_dot_part[(size_t)s*BSZ*BSZ + i*BSZ + j];
    float d2 = g_norm[i] + g_norm[BSZ + j] - 2.f * dot;
    float d = sqrtf(fmaxf(d2, 0.f));
    g_dist[i*BSZ + j] = d;

    __shared__ float red[BSZ];
    red[j] = d; __syncthreads();
    for (int off = 64; off > 0; off >>= 1) {
        if (j < off) red[j] = fmaxf(red[j], red[j + off]);
        __syncthreads();
    }
    float mx = red[0]; __syncthreads();
    red[j] = expf(d - mx); __syncthreads();
    for (int off = 64; off > 0; off >>= 1) {
        if (j < off) red[j] += red[j + off];
        __syncthreads();
    }
    if (j == 0) g_lse[i] = mx + logf(red[0]);
}

// ---------------- packed 2D FFT: register radix-16x8, 512 threads ----------------
// One packed image z = x1[b] + i*x2[b] per CTA. Output digit-permuted by sig2
// per dimension (PSD stats are permutation-invariant; tau2 handles -k pairing).
__global__ __launch_bounds__(512, 1) void fft_psd_kernel(const float* __restrict__ x1, const float* __restrict__ x2) {
    extern __shared__ float sm[];
    float* SRe = sm;                               // [128][PITCHF]
    float* SIm = sm + 128*PITCHF;
    __shared__ float2 tw[128];
    __shared__ float nb1[16], nb2[16];
    int b = blockIdx.x;
    const float* sa = x1 + (size_t)b*NPIX;
    const float* sb = x2 + (size_t)b*NPIX;
    int tid = threadIdx.x;

    if (tid < 128) {
        float sn, cs;
        sincospif((float)tid / 64.f, &sn, &cs);
        tw[tid] = make_float2(cs, -sn);            // W128^tid
    }
    __syncthreads();                               // tw visible to ALL warps (race fix)

    // ===== phase 1: rows, 16-pt stage (gmem -> regs -> smem skewed) + norms =====
    float s1 = 0.f, s2 = 0.f;
#pragma unroll
    for (int h = 0; h < 2; h++) {
        int item = tid + 512*h;
        int r = item >> 3, n = item & 7;
        float xr[16], xi[16];
#pragma unroll
        for (int s = 0; s < 16; s++) {
            float a  = sa[r*128 + n + 8*s];
            float bb = sb[r*128 + n + 8*s];
            xr[s] = a; xi[s] = bb;
            s1 += a*a; s2 += bb*bb;
        }
        fft16(xr, xi, tw);
#pragma unroll
        for (int sl = 0; sl < 16; sl++) {
            int e1 = sl >> 2, e2 = sl & 3;
            int d = e1 + 4*e2;
            float vr = xr[sl], vi = xi[sl];
            if (d) cmul_ip(vr, vi, tw[n*d]);
            int col = 8*((d + r) & 15) + n;
            SRe[r*PITCHF + col] = vr;
            SIm[r*PITCHF + col] = vi;
        }
    }
#pragma unroll
    for (int o = 16; o; o >>= 1) {
        s1 += __shfl_down_sync(0xffffffffu, s1, o);
        s2 += __shfl_down_sync(0xffffffffu, s2, o);
    }
    if ((tid & 31) == 0) { nb1[tid>>5] = s1; nb2[tid>>5] = s2; }
    __syncthreads();                               // phase-1 smem writes + nb staged
    if (tid < 16) {
        float a = nb1[tid], c = nb2[tid];
#pragma unroll
        for (int o = 8; o; o >>= 1) {
            a += __shfl_down_sync(0xffffu, a, o);
            c += __shfl_down_sync(0xffffu, c, o);
        }
        if (tid == 0) { g_norm[b] = a; g_norm[b + BSZ] = c; }
    }

    // ===== phase 2: rows, 8-pt stage; two row-halves, staged reads =====
#pragma unroll
    for (int half = 0; half < 2; half++) {
        float yr[2][8], yi[2][8];
#pragma unroll
        for (int u = 0; u < 2; u++) {
            int i = tid + 512*u;
            int row = half*64 + (i & 63);
            int d1 = i >> 6;
            int cb = row*PITCHF + 8*((d1 + row) & 15);
#pragma unroll
            for (int k = 0; k < 8; k++) { yr[u][k] = SRe[cb+k]; yi[u][k] = SIm[cb+k]; }
        }
        __syncthreads();                           // all reads done before writes
#pragma unroll
        for (int u = 0; u < 2; u++) {
            int i = tid + 512*u;
            int row = half*64 + (i & 63);
            int d1 = i >> 6;
            fft8(yr[u], yi[u], tw);
            int ob = row*PITCHF + 8*d1;
#pragma unroll
            for (int f2 = 0; f2 < 4; f2++) {
                SRe[ob + 2*f2]     = yr[u][f2];     // k' = 2*f2
                SIm[ob + 2*f2]     = yi[u][f2];
                SRe[ob + 2*f2 + 1] = yr[u][4+f2];   // k' = 1 + 2*f2
                SIm[ob + 2*f2 + 1] = yi[u][4+f2];
            }
        }
        __syncthreads();
    }

    // ===== phase 3: cols, 16-pt stage (in-place per thread; residue-disjoint) =====
#pragma unroll
    for (int u = 0; u < 2; u++) {
        int item = tid + 512*u;
        int c = item & 127, n3 = (item >> 7) & 7;
        float zr[16], zi[16];
#pragma unroll
        for (int s = 0; s < 16; s++) {
            int m = n3 + 8*s;
            zr[s] = SRe[m*PITCHF + c];
            zi[s] = SIm[m*PITCHF + c];
        }
        fft16(zr, zi, tw);
#pragma unroll
        for (int sl = 0; sl < 16; sl++) {
            int e1 = sl >> 2, e2 = sl & 3;
            int d = e1 + 4*e2;
            float vr = zr[sl], vi = zi[sl];
            if (d) cmul_ip(vr, vi, tw[n3*d]);
            SRe[(8*d + n3)*PITCHF + c] = vr;
            SIm[(8*d + n3)*PITCHF + c] = vi;
        }
    }
    __syncthreads();

    // ===== phase 4: cols, 8-pt stage + |Z|^2 -> gmem =====
#pragma unroll
    for (int u = 0; u < 4; u++) {
        int item = tid + 512*u;
        int c4 = item & 127, d1 = item >> 7;       // d1 in [0,16)
        float wr[8], wi[8];
#pragma unroll
        for (int k = 0; k < 8; k++) {
            wr[k] = SRe[(8*d1 + k)*PITCHF + c4];
            wi[k] = SIm[(8*d1 + k)*PITCHF + c4];
        }
        fft8(wr, wi, tw);
        float* dst = g_psd + (size_t)b*NPIX + c4;
#pragma unroll
        for (int f2 = 0; f2 < 4; f2++) {
            dst[(8*d1 + 2*f2    )*128] = wr[f2]*wr[f2] + wi[f2]*wi[f2];
            dst[(8*d1 + 2*f2 + 1)*128] = wr[4+f2]*wr[4+f2] + wi[4+f2]*wi[4+f2];
        }
    }
}

// ---------------- S partials: 32 image-groups x 4 images, float4 ----------------
__global__ __launch_bounds__(256) void psd_reduce_kernel() {
    int t = blockIdx.x * 256 + threadIdx.x;        // quad index 0..4095
    int imgbase = blockIdx.y * 4;
    const float4* src = reinterpret_cast<const float4*>(g_psd);
    float4 s = make_float4(0.f, 0.f, 0.f, 0.f);
#pragma unroll
    for (int i = 0; i < 4; i++) {
        float4 v = src[(size_t)(imgbase + i)*(NPIX/4) + t];
        s.x += v.x; s.y += v.y; s.z += v.z; s.w += v.w;
    }
    reinterpret_cast<float4*>(g_S)[(size_t)blockIdx.y*(NPIX/4) + t] = s;
}

// ---------------- per-bin avgpsd via -k pairing (tau2), float log ----------------
__global__ void psd_stats_kernel() {
    int p = blockIdx.x * 128 + threadIdx.x;
    int pr = p >> 7, pc = p & 127;
    int q = tau2(pr) * 128 + tau2(pc);
    double Sp = 0.0, Sq = 0.0;
#pragma unroll
    for (int h = 0; h < NGRP; h++) { Sp += (double)g_S[h*NPIX + p]; Sq += (double)g_S[h*NPIX + q]; }
    double avg = (Sp + Sq) * (1.0 / 512.0);
    __shared__ double shl[128];
    __shared__ double sha[128];
    shl[threadIdx.x] = (double)logf((float)avg);
    sha[threadIdx.x] = avg;
    __syncthreads();
    for (int off = 64; off > 0; off >>= 1) {
        if (threadIdx.x < off) {
            shl[threadIdx.x] += shl[threadIdx.x + off];
            sha[threadIdx.x] += sha[threadIdx.x + off];
        }
        __syncthreads();
    }
    if (threadIdx.x == 0) { g_red_log[blockIdx.x] = shl[0]; g_red_avg[blockIdx.x] = sha[0]; }
}

// ---------------- final scalar ----------------
__global__ void final_kernel(float* __restrict__ out) {
    __shared__ double sh[128];
    int t = threadIdx.x;

    sh[t] = (double)(g_lse[t] - g_dist[t*BSZ + t]);
    __syncthreads();
    for (int off = 64; off > 0; off >>= 1) {
        if (t < off) sh[t] += sh[t + off];
        __syncthreads();
    }
    double ce = sh[0] / (double)BSZ;
    __syncthreads();

    sh[t] = g_red_log[t]; __syncthreads();
    for (int off = 64; off > 0; off >>= 1) {
        if (t < off) sh[t] += sh[t + off];
        __syncthreads();
    }
    double slog = sh[0];
    __syncthreads();

    sh[t] = g_red_avg[t]; __syncthreads();
    for (int off = 64; off > 0; off >>= 1) {
        if (t < off) sh[t] += sh[t + off];
        __syncthreads();
    }
    double savg = sh[0];

    if (t == 0) {
        double r = slog / (double)NPIX - log(savg / (double)NPIX);
        out[0] = (float)(ce - 0.1 * r);
    }
}

// ---------------- launch ----------------
extern "C" void kernel_launch(void* const* d_in, const int* in_sizes, int n_in,
                              void* d_out, int out_size) {
    const float* x1 = (const float*)d_in[0];
    const float* x2 = (const float*)d_in[1];
    float* out = (float*)d_out;

    const int smem = 2 * 128 * PITCHF * (int)sizeof(float);   // 132096 B
    cudaFuncSetAttribute(fft_psd_kernel, cudaFuncAttributeMaxDynamicSharedMemorySize, smem);

    fft_psd_kernel<<<NPACK, 512, smem>>>(x1, x2);
    dot_kernel<<<dim3(2, 1, GK), 256>>>(x1, x2);
    dist_lse_kernel<<<BSZ, BSZ>>>();
    psd_reduce_kernel<<<dim3(16, NGRP), 256>>>();
    psd_stats_kernel<<<128, 128>>>();
    final_kernel<<<1, 128>>>(out);
}